// round 13
// baseline (speedup 1.0000x reference)
#include <cuda_runtime.h>
#include <cstdint>

// Problem constants
#define BB   2
#define SS   2048
#define DIMM 1024
#define HH   16
#define DD   64
#define FF   32      // S / 64
#define EPSF 1e-6f

// Scratch (static device globals; no dynamic allocation)
__device__ float g_raw[3][BB * SS * DIMM];        // raw projections [b,s,dim]
__device__ float g_T[3][BB * HH * SS * DD];       // q,k,v in [b,h,s,d]

// ---------------------------------------------------------------------------
// SGEMM: C[m,n] = sum_k X[m,k] * W[n,k]   (X: 4096x1024, W: 1024x1024)
// blockIdx.z selects wq/wk/wv. Tile 128x128xBK8, 256 threads, 8x8/thread.
// Register-prefetch pipeline: next k-slab global loads issued right after the
// post-store barrier, consumed only after the FMA block.
// ---------------------------------------------------------------------------
__global__ __launch_bounds__(256) void sgemm_nt(const float* __restrict__ X,
                                                const float* __restrict__ Wq,
                                                const float* __restrict__ Wk,
                                                const float* __restrict__ Wv)
{
    const float* W = (blockIdx.z == 0) ? Wq : (blockIdx.z == 1 ? Wk : Wv);
    float* C = g_raw[blockIdx.z];

    __shared__ float As[8][132];
    __shared__ float Bs[8][132];

    int tid = threadIdx.x;
    int m0 = blockIdx.y * 128, n0 = blockIdx.x * 128;
    int tx = tid & 15, ty = tid >> 4;

    float acc[8][8];
#pragma unroll
    for (int i = 0; i < 8; i++)
#pragma unroll
        for (int jj = 0; jj < 8; jj++) acc[i][jj] = 0.f;

    int lr = tid >> 1;         // 0..127 row of tile
    int lc = (tid & 1) * 4;    // 0 or 4 (k offset)
    const float* Aptr = X + (size_t)(m0 + lr) * 1024 + lc;
    const float* Bptr = W + (size_t)(n0 + lr) * 1024 + lc;

    float4 av = *(const float4*)(Aptr);
    float4 bv = *(const float4*)(Bptr);

    for (int k0 = 0; k0 < 1024; k0 += 8) {
        As[lc + 0][lr] = av.x; As[lc + 1][lr] = av.y;
        As[lc + 2][lr] = av.z; As[lc + 3][lr] = av.w;
        Bs[lc + 0][lr] = bv.x; Bs[lc + 1][lr] = bv.y;
        Bs[lc + 2][lr] = bv.z; Bs[lc + 3][lr] = bv.w;
        __syncthreads();

        if (k0 + 8 < 1024) {
            av = *(const float4*)(Aptr + k0 + 8);
            bv = *(const float4*)(Bptr + k0 + 8);
        }

#pragma unroll
        for (int kk = 0; kk < 8; kk++) {
            float a[8], b[8];
#pragma unroll
            for (int u = 0; u < 8; u++) a[u] = As[kk][ty * 8 + u];
#pragma unroll
            for (int u = 0; u < 8; u++) b[u] = Bs[kk][tx * 8 + u];
#pragma unroll
            for (int i = 0; i < 8; i++)
#pragma unroll
                for (int jj = 0; jj < 8; jj++)
                    acc[i][jj] = fmaf(a[i], b[jj], acc[i][jj]);
        }
        __syncthreads();
    }
#pragma unroll
    for (int i = 0; i < 8; i++) {
        float4 v0 = make_float4(acc[i][0], acc[i][1], acc[i][2], acc[i][3]);
        float4 v1 = make_float4(acc[i][4], acc[i][5], acc[i][6], acc[i][7]);
        float* cp = C + (size_t)(m0 + ty * 8 + i) * 1024 + n0 + tx * 8;
        *(float4*)cp = v0;
        *(float4*)(cp + 4) = v1;
    }
}

// ---------------------------------------------------------------------------
// Epilogue: rmsnorm(q,k) + rope + scale, transpose all to [b,h,s,d]
// ---------------------------------------------------------------------------
__global__ __launch_bounds__(128) void qkv_epilogue(const float* __restrict__ cosT,
                                                    const float* __restrict__ sinT,
                                                    const float* __restrict__ gq,
                                                    const float* __restrict__ gk)
{
    int warp = blockIdx.x * 4 + (threadIdx.x >> 5);
    int lane = threadIdx.x & 31;
    int h  = warp & 15;
    int bs = warp >> 4;           // b*S + s
    int s  = bs & (SS - 1);
    int b  = bs >> 11;
    int d0 = lane * 2, d1 = d0 + 1;
    size_t src = (size_t)bs * 1024 + h * 64;
    size_t dst = ((size_t)(b * HH + h) * SS + s) * 64;

    float c  = cosT[s * 64 + d0];
    float sn = sinT[s * 64 + d0];
    const float SCALE = 0.35355339059327373f;   // 64^-0.25

    // Q
    {
        float x0 = g_raw[0][src + d0], x1 = g_raw[0][src + d1];
        float ssum = x0 * x0 + x1 * x1;
#pragma unroll
        for (int m = 16; m > 0; m >>= 1) ssum += __shfl_xor_sync(0xffffffffu, ssum, m);
        float r = rsqrtf(ssum * (1.0f / 64.0f) + EPSF);
        x0 *= r * gq[d0]; x1 *= r * gq[d1];
        g_T[0][dst + d0] = (x0 * c - x1 * sn) * SCALE;
        g_T[0][dst + d1] = (x1 * c + x0 * sn) * SCALE;
    }
    // K
    {
        float x0 = g_raw[1][src + d0], x1 = g_raw[1][src + d1];
        float ssum = x0 * x0 + x1 * x1;
#pragma unroll
        for (int m = 16; m > 0; m >>= 1) ssum += __shfl_xor_sync(0xffffffffu, ssum, m);
        float r = rsqrtf(ssum * (1.0f / 64.0f) + EPSF);
        x0 *= r * gk[d0]; x1 *= r * gk[d1];
        g_T[1][dst + d0] = (x0 * c - x1 * sn) * SCALE;
        g_T[1][dst + d1] = (x1 * c + x0 * sn) * SCALE;
    }
    // V (plain transpose)
    g_T[2][dst + d0] = g_raw[2][src + d0];
    g_T[2][dst + d1] = g_raw[2][src + d1];
}

// ---------------------------------------------------------------------------
// Monarch iterations. One CTA per (b,h,g). 512 threads.
// tid = a*64 + j*8 + t8 : a = warp-pair id (k-row / i-row owner, warp-uniform),
// j = 0..7, t8 = d-chunk of 8 floats.
// Shared: Ls[32][8][68] (L/M, padded), Rs[32][8][8][8], Ks[2][4096] (K/V tiles),
//         Os[64][68] o-tile.
// ---------------------------------------------------------------------------
#define LS_FLOATS  (32 * 8 * 68)          // 17408
#define RS_FLOATS  (32 * 8 * 8 * 8)       // 16384
#define KS_FLOATS  (2 * 4096)             // 8192
#define OS_FLOATS  (64 * 68)              // 4352
#define SMEM_FLOATS (LS_FLOATS + RS_FLOATS + KS_FLOATS + OS_FLOATS)
#define SMEM_BYTES  (SMEM_FLOATS * 4)

__device__ __forceinline__ void issue_tile(int step, int g,
                                           const float* __restrict__ Kp,
                                           const float* __restrict__ Vp,
                                           uint32_t Ks_base, int tid)
{
    int per   = g + 1;
    int phase = step / per;                  // 0,1 -> K ; 2 -> V
    int f     = step - phase * per;
    const float* src = ((phase < 2) ? Kp : Vp) + (size_t)f * 4096;
    uint32_t dstb = Ks_base + (uint32_t)(step & 1) * (4096u * 4u);
#pragma unroll
    for (int u = 0; u < 2; u++) {
        int idx4 = tid + u * 512;
        asm volatile("cp.async.cg.shared.global [%0], [%1], 16;"
                     :: "r"(dstb + idx4 * 16), "l"(src + idx4 * 4) : "memory");
    }
    asm volatile("cp.async.commit_group;" ::: "memory");
}

__global__ void __launch_bounds__(512, 1) monarch_kernel(float* __restrict__ out)
{
    const int g = (FF - 1) - blockIdx.x;   // largest work first
    const int h = blockIdx.y, b = blockIdx.z;
    const int tid = threadIdx.x;
    const int t8  = tid & 7;
    const int grp = tid >> 3;
    const int j   = grp & 7;
    const int a   = grp >> 3;    // = tid>>6, warp-uniform

    extern __shared__ float sm[];
    float* Ls = sm;
    float* Rs = sm + LS_FLOATS;
    float* Ks = Rs + RS_FLOATS;
    float* Os = Ks + KS_FLOATS;
    uint32_t Ks_base = (uint32_t)__cvta_generic_to_shared(Ks);

    const int bh = b * HH + h;
    const float* Q  = g_T[0] + ((size_t)bh * SS + g * 64) * 64;
    const float* Kp = g_T[1] + (size_t)bh * SS * 64;
    const float* Vp = g_T[2] + (size_t)bh * SS * 64;

    // init L[f][j][k][i] = (f<=g) * delta(k,i)
    for (int idx = tid; idx < 32 * 8 * 64; idx += 512) {
        int f   = idx >> 9;
        int rem = idx & 511;
        int jj  = rem >> 6;
        int e   = rem & 63;
        int k   = e >> 3, i = e & 7;
        Ls[(f * 8 + jj) * 68 + e] = (f <= g && k == i) ? 1.0f : 0.0f;
    }

    // q block -> registers: qreg[i][dd], thread owns (j, d-chunk t8)
    float qreg[8][8];
#pragma unroll
    for (int i = 0; i < 8; i++) {
        const float4* qp = (const float4*)(Q + (i * 8 + j) * 64 + t8 * 8);
        float4 v0 = qp[0], v1 = qp[1];
        qreg[i][0] = v0.x; qreg[i][1] = v0.y; qreg[i][2] = v0.z; qreg[i][3] = v0.w;
        qreg[i][4] = v1.x; qreg[i][5] = v1.y; qreg[i][6] = v1.z; qreg[i][7] = v1.w;
    }
    __syncthreads();

    const int nsteps = 3 * (g + 1);
    issue_tile(0, g, Kp, Vp, Ks_base, tid);
    int step = 0;

    const float NEGINF = __int_as_float(0xff800000);

    for (int it = 0; it < 2; it++) {
        for (int f = 0; f <= g; f++, step++) {
            if (step + 1 < nsteps) {
                issue_tile(step + 1, g, Kp, Vp, Ks_base, tid);
                asm volatile("cp.async.wait_group 1;" ::: "memory");
            } else {
                asm volatile("cp.async.wait_group 0;" ::: "memory");
            }
            __syncthreads();

            const float* kt = Ks + (step & 1) * 4096 + a * 512;   // k-row a: [l][64]
            float* Lrow = Ls + (f * 8 + j) * 68 + a * 8;

            float Lw[8];
#pragma unroll
            for (int i = 0; i < 8; i++) Lw[i] = Lrow[i];
            float cR = 0.f;
#pragma unroll
            for (int i = 0; i < 8; i++) cR += Lw[i];

            // aR[dd] = sum_i Lw[i] * q[i][dd]
            float aR[8];
#pragma unroll
            for (int dd = 0; dd < 8; dd++) {
                float s = 0.f;
#pragma unroll
                for (int i = 0; i < 8; i++) s = fmaf(Lw[i], qreg[i][dd], s);
                aR[dd] = s;
            }

            // bR partials over this thread's d-chunk
            float p[8];
#pragma unroll
            for (int l = 0; l < 8; l++) {
                const float* kv = kt + l * 64 + t8 * 8;
                float s = 0.f;
#pragma unroll
                for (int dd = 0; dd < 8; dd++) s = fmaf(aR[dd], kv[dd], s);
                p[l] = s;
            }
#pragma unroll
            for (int l = 0; l < 8; l++) {
                p[l] += __shfl_xor_sync(0xffffffffu, p[l], 1);
                p[l] += __shfl_xor_sync(0xffffffffu, p[l], 2);
                p[l] += __shfl_xor_sync(0xffffffffu, p[l], 4);
            }

            // softmax over l of bR/(cR+eps)
            float inv = 1.0f / (cR + EPSF);
            float mx = NEGINF;
#pragma unroll
            for (int l = 0; l < 8; l++) { p[l] *= inv; mx = fmaxf(mx, p[l]); }
            float ssum = 0.f;
#pragma unroll
            for (int l = 0; l < 8; l++) { p[l] = __expf(p[l] - mx); ssum += p[l]; }
            float rinv = 1.0f / ssum;
            float cL = 0.f;
#pragma unroll
            for (int l = 0; l < 8; l++) {
                p[l] *= rinv;
                cL = fmaf(p[l], __logf(fmaxf(p[l], 1e-38f)), cL);
            }

            if (t8 == 0) {
                float* rp = Rs + ((f * 8 + a) * 8 + j) * 8;
#pragma unroll
                for (int l = 0; l < 8; l++) rp[l] = p[l];
            }

            // aL[dd] = sum_l R[l] * k[l][dd]
            float aL[8];
#pragma unroll
            for (int dd = 0; dd < 8; dd++) aL[dd] = 0.f;
#pragma unroll
            for (int l = 0; l < 8; l++) {
                const float* kv = kt + l * 64 + t8 * 8;
#pragma unroll
                for (int dd = 0; dd < 8; dd++) aL[dd] = fmaf(p[l], kv[dd], aL[dd]);
            }

            // bL[i] = sum_d aL[dd] * q[i][dd]  (partial, then 8-lane reduce)
            float bL[8];
#pragma unroll
            for (int i = 0; i < 8; i++) {
                float s = 0.f;
#pragma unroll
                for (int dd = 0; dd < 8; dd++) s = fmaf(aL[dd], qreg[i][dd], s);
                bL[i] = s;
            }
#pragma unroll
            for (int i = 0; i < 8; i++) {
                bL[i] += __shfl_xor_sync(0xffffffffu, bL[i], 1);
                bL[i] += __shfl_xor_sync(0xffffffffu, bL[i], 2);
                bL[i] += __shfl_xor_sync(0xffffffffu, bL[i], 4);
            }

            // M overwrite L (same group owns this row segment)
            if (t8 == 0) {
#pragma unroll
                for (int i = 0; i < 8; i++) Lrow[i] = bL[i] - cL;
            }
            __syncthreads();
        }

        // L softmax over (f<=g, k) for each (j, i=a); t8 strides f
        {
            float mx = NEGINF;
            for (int f = t8; f <= g; f += 8) {
                const float* Mr = Ls + (f * 8 + j) * 68;
#pragma unroll
                for (int k = 0; k < 8; k++) mx = fmaxf(mx, Mr[k * 8 + a]);
            }
            mx = fmaxf(mx, __shfl_xor_sync(0xffffffffu, mx, 1));
            mx = fmaxf(mx, __shfl_xor_sync(0xffffffffu, mx, 2));
            mx = fmaxf(mx, __shfl_xor_sync(0xffffffffu, mx, 4));
            float ssum = 0.f;
            for (int f = t8; f <= g; f += 8) {
                const float* Mr = Ls + (f * 8 + j) * 68;
#pragma unroll
                for (int k = 0; k < 8; k++) ssum += __expf(Mr[k * 8 + a] - mx);
            }
            ssum += __shfl_xor_sync(0xffffffffu, ssum, 1);
            ssum += __shfl_xor_sync(0xffffffffu, ssum, 2);
            ssum += __shfl_xor_sync(0xffffffffu, ssum, 4);
            float rs = 1.0f / ssum;
            for (int f = t8; f <= g; f += 8) {
                float* Mr = Ls + (f * 8 + j) * 68;
#pragma unroll
                for (int k = 0; k < 8; k++)
                    Mr[k * 8 + a] = __expf(Mr[k * 8 + a] - mx) * rs;
            }
        }
        __syncthreads();
    }

    // o / out: out[i,j,d] = sum_{f,k} L[f,j,k,i] * (sum_l R[f,k,j,l] v[f,k,l,d])
    float oacc[8];
#pragma unroll
    for (int dd = 0; dd < 8; dd++) oacc[dd] = 0.f;

    for (int f = 0; f <= g; f++, step++) {
        if (step + 1 < nsteps) {
            issue_tile(step + 1, g, Kp, Vp, Ks_base, tid);
            asm volatile("cp.async.wait_group 1;" ::: "memory");
        } else {
            asm volatile("cp.async.wait_group 0;" ::: "memory");
        }
        __syncthreads();

        const float* vt = Ks + (step & 1) * 4096 + a * 512;   // v-row k=a
        // phase A: o_f[k=a][j][dchunk]
        const float* rp = Rs + ((f * 8 + a) * 8 + j) * 8;
        float Rv[8];
#pragma unroll
        for (int l = 0; l < 8; l++) Rv[l] = rp[l];
        float ov[8];
#pragma unroll
        for (int dd = 0; dd < 8; dd++) ov[dd] = 0.f;
#pragma unroll
        for (int l = 0; l < 8; l++) {
            const float* vv = vt + l * 64 + t8 * 8;
#pragma unroll
            for (int dd = 0; dd < 8; dd++) ov[dd] = fmaf(Rv[l], vv[dd], ov[dd]);
        }
        float* op = Os + (a * 8 + j) * 68 + t8 * 8;
#pragma unroll
        for (int dd = 0; dd < 8; dd++) op[dd] = ov[dd];
        __syncthreads();

        // phase B: out[i=a][j][dchunk] += sum_k L[f][j][k][i] * o_f[k][j][dchunk]
        const float* Lrow = Ls + (f * 8 + j) * 68;
#pragma unroll
        for (int k = 0; k < 8; k++) {
            float lw = Lrow[k * 8 + a];
            const float* op2 = Os + (k * 8 + j) * 68 + t8 * 8;
#pragma unroll
            for (int dd = 0; dd < 8; dd++) oacc[dd] = fmaf(lw, op2[dd], oacc[dd]);
        }
        __syncthreads();
    }

    // write out[b][g*64 + i*8 + j][h*64 + d]
    float* po = out + ((size_t)b * SS + g * 64 + a * 8 + j) * DIMM + h * 64 + t8 * 8;
    *(float4*)(po + 0) = make_float4(oacc[0], oacc[1], oacc[2], oacc[3]);
    *(float4*)(po + 4) = make_float4(oacc[4], oacc[5], oacc[6], oacc[7]);
}

// ---------------------------------------------------------------------------
extern "C" void kernel_launch(void* const* d_in, const int* in_sizes, int n_in,
                              void* d_out, int out_size)
{
    const float* x    = (const float*)d_in[0];
    const float* cosT = (const float*)d_in[1];
    const float* sinT = (const float*)d_in[2];
    const float* wq   = (const float*)d_in[3];
    const float* wk   = (const float*)d_in[4];
    const float* wv   = (const float*)d_in[5];
    const float* gq   = (const float*)d_in[6];
    const float* gk   = (const float*)d_in[7];
    float* out = (float*)d_out;

    cudaFuncSetAttribute(monarch_kernel,
                         cudaFuncAttributeMaxDynamicSharedMemorySize, SMEM_BYTES);

    sgemm_nt<<<dim3(8, 32, 3), 256>>>(x, wq, wk, wv);
    qkv_epilogue<<<(BB * SS * HH) / 4, 128>>>(cosT, sinT, gq, gk);
    monarch_kernel<<<dim3(FF, HH, BB), 512, SMEM_BYTES>>>(out);
}

// round 14
// speedup vs baseline: 1.0005x; 1.0005x over previous
#include <cuda_runtime.h>
#include <cstdint>

// Problem constants
#define BB   2
#define SS   2048
#define DIMM 1024
#define HH   16
#define DD   64
#define FF   32      // S / 64
#define EPSF 1e-6f

// Scratch (static device globals; no dynamic allocation)
__device__ float g_raw[3][BB * SS * DIMM];        // raw projections [b,s,dim]
__device__ float g_T[3][BB * HH * SS * DD];       // q,k,v in [b,h,s,d]

// ---------------------------------------------------------------------------
// SGEMM: C[m,n] = sum_k X[m,k] * W[n,k]   (X: 4096x1024, W: 1024x1024)
// blockIdx.z selects wq/wk/wv. Tile 128x128xBK8, 256 threads, 8x8/thread.
// Register-prefetch pipeline: next k-slab global loads issued right after the
// post-store barrier, consumed only after the FMA block.
// ---------------------------------------------------------------------------
__global__ __launch_bounds__(256) void sgemm_nt(const float* __restrict__ X,
                                                const float* __restrict__ Wq,
                                                const float* __restrict__ Wk,
                                                const float* __restrict__ Wv)
{
    const float* W = (blockIdx.z == 0) ? Wq : (blockIdx.z == 1 ? Wk : Wv);
    float* C = g_raw[blockIdx.z];

    __shared__ float As[8][132];
    __shared__ float Bs[8][132];

    int tid = threadIdx.x;
    int m0 = blockIdx.y * 128, n0 = blockIdx.x * 128;
    int tx = tid & 15, ty = tid >> 4;

    float acc[8][8];
#pragma unroll
    for (int i = 0; i < 8; i++)
#pragma unroll
        for (int jj = 0; jj < 8; jj++) acc[i][jj] = 0.f;

    int lr = tid >> 1;         // 0..127 row of tile
    int lc = (tid & 1) * 4;    // 0 or 4 (k offset)
    const float* Aptr = X + (size_t)(m0 + lr) * 1024 + lc;
    const float* Bptr = W + (size_t)(n0 + lr) * 1024 + lc;

    float4 av = *(const float4*)(Aptr);
    float4 bv = *(const float4*)(Bptr);

    for (int k0 = 0; k0 < 1024; k0 += 8) {
        As[lc + 0][lr] = av.x; As[lc + 1][lr] = av.y;
        As[lc + 2][lr] = av.z; As[lc + 3][lr] = av.w;
        Bs[lc + 0][lr] = bv.x; Bs[lc + 1][lr] = bv.y;
        Bs[lc + 2][lr] = bv.z; Bs[lc + 3][lr] = bv.w;
        __syncthreads();

        if (k0 + 8 < 1024) {
            av = *(const float4*)(Aptr + k0 + 8);
            bv = *(const float4*)(Bptr + k0 + 8);
        }

#pragma unroll
        for (int kk = 0; kk < 8; kk++) {
            float a[8], b[8];
#pragma unroll
            for (int u = 0; u < 8; u++) a[u] = As[kk][ty * 8 + u];
#pragma unroll
            for (int u = 0; u < 8; u++) b[u] = Bs[kk][tx * 8 + u];
#pragma unroll
            for (int i = 0; i < 8; i++)
#pragma unroll
                for (int jj = 0; jj < 8; jj++)
                    acc[i][jj] = fmaf(a[i], b[jj], acc[i][jj]);
        }
        __syncthreads();
    }
#pragma unroll
    for (int i = 0; i < 8; i++) {
        float4 v0 = make_float4(acc[i][0], acc[i][1], acc[i][2], acc[i][3]);
        float4 v1 = make_float4(acc[i][4], acc[i][5], acc[i][6], acc[i][7]);
        float* cp = C + (size_t)(m0 + ty * 8 + i) * 1024 + n0 + tx * 8;
        *(float4*)cp = v0;
        *(float4*)(cp + 4) = v1;
    }
}

// ---------------------------------------------------------------------------
// Epilogue: rmsnorm(q,k) + rope + scale, transpose all to [b,h,s,d]
// ---------------------------------------------------------------------------
__global__ __launch_bounds__(128) void qkv_epilogue(const float* __restrict__ cosT,
                                                    const float* __restrict__ sinT,
                                                    const float* __restrict__ gq,
                                                    const float* __restrict__ gk)
{
    int warp = blockIdx.x * 4 + (threadIdx.x >> 5);
    int lane = threadIdx.x & 31;
    int h  = warp & 15;
    int bs = warp >> 4;           // b*S + s
    int s  = bs & (SS - 1);
    int b  = bs >> 11;
    int d0 = lane * 2, d1 = d0 + 1;
    size_t src = (size_t)bs * 1024 + h * 64;
    size_t dst = ((size_t)(b * HH + h) * SS + s) * 64;

    float c  = cosT[s * 64 + d0];
    float sn = sinT[s * 64 + d0];
    const float SCALE = 0.35355339059327373f;   // 64^-0.25

    // Q
    {
        float x0 = g_raw[0][src + d0], x1 = g_raw[0][src + d1];
        float ssum = x0 * x0 + x1 * x1;
#pragma unroll
        for (int m = 16; m > 0; m >>= 1) ssum += __shfl_xor_sync(0xffffffffu, ssum, m);
        float r = rsqrtf(ssum * (1.0f / 64.0f) + EPSF);
        x0 *= r * gq[d0]; x1 *= r * gq[d1];
        g_T[0][dst + d0] = (x0 * c - x1 * sn) * SCALE;
        g_T[0][dst + d1] = (x1 * c + x0 * sn) * SCALE;
    }
    // K
    {
        float x0 = g_raw[1][src + d0], x1 = g_raw[1][src + d1];
        float ssum = x0 * x0 + x1 * x1;
#pragma unroll
        for (int m = 16; m > 0; m >>= 1) ssum += __shfl_xor_sync(0xffffffffu, ssum, m);
        float r = rsqrtf(ssum * (1.0f / 64.0f) + EPSF);
        x0 *= r * gk[d0]; x1 *= r * gk[d1];
        g_T[1][dst + d0] = (x0 * c - x1 * sn) * SCALE;
        g_T[1][dst + d1] = (x1 * c + x0 * sn) * SCALE;
    }
    // V (plain transpose)
    g_T[2][dst + d0] = g_raw[2][src + d0];
    g_T[2][dst + d1] = g_raw[2][src + d1];
}

// ---------------------------------------------------------------------------
// Monarch iterations. One CTA per (b,h,g). 512 threads.
// tid = a*64 + j*8 + t8 : a = warp-pair id (k-row / i-row owner, warp-uniform),
// j = 0..7, t8 = d-chunk of 8 floats.
// Shared: Ls[32][8][68] (L/M, padded), Rs[32][8][8][8], Ks[2][4096] (K/V tiles),
//         Os[64][68] o-tile.
// ---------------------------------------------------------------------------
#define LS_FLOATS  (32 * 8 * 68)          // 17408
#define RS_FLOATS  (32 * 8 * 8 * 8)       // 16384
#define KS_FLOATS  (2 * 4096)             // 8192
#define OS_FLOATS  (64 * 68)              // 4352
#define SMEM_FLOATS (LS_FLOATS + RS_FLOATS + KS_FLOATS + OS_FLOATS)
#define SMEM_BYTES  (SMEM_FLOATS * 4)

__device__ __forceinline__ void issue_tile(int step, int g,
                                           const float* __restrict__ Kp,
                                           const float* __restrict__ Vp,
                                           uint32_t Ks_base, int tid)
{
    int per   = g + 1;
    int phase = step / per;                  // 0,1 -> K ; 2 -> V
    int f     = step - phase * per;
    const float* src = ((phase < 2) ? Kp : Vp) + (size_t)f * 4096;
    uint32_t dstb = Ks_base + (uint32_t)(step & 1) * (4096u * 4u);
#pragma unroll
    for (int u = 0; u < 2; u++) {
        int idx4 = tid + u * 512;
        asm volatile("cp.async.cg.shared.global [%0], [%1], 16;"
                     :: "r"(dstb + idx4 * 16), "l"(src + idx4 * 4) : "memory");
    }
    asm volatile("cp.async.commit_group;" ::: "memory");
}

__global__ void __launch_bounds__(512, 1) monarch_kernel(float* __restrict__ out)
{
    const int g = (FF - 1) - blockIdx.x;   // largest work first
    const int h = blockIdx.y, b = blockIdx.z;
    const int tid = threadIdx.x;
    const int t8  = tid & 7;
    const int grp = tid >> 3;
    const int j   = grp & 7;
    const int a   = grp >> 3;    // = tid>>6, warp-uniform

    extern __shared__ float sm[];
    float* Ls = sm;
    float* Rs = sm + LS_FLOATS;
    float* Ks = Rs + RS_FLOATS;
    float* Os = Ks + KS_FLOATS;
    uint32_t Ks_base = (uint32_t)__cvta_generic_to_shared(Ks);

    const int bh = b * HH + h;
    const float* Q  = g_T[0] + ((size_t)bh * SS + g * 64) * 64;
    const float* Kp = g_T[1] + (size_t)bh * SS * 64;
    const float* Vp = g_T[2] + (size_t)bh * SS * 64;

    // init L[f][j][k][i] = (f<=g) * delta(k,i)
    for (int idx = tid; idx < 32 * 8 * 64; idx += 512) {
        int f   = idx >> 9;
        int rem = idx & 511;
        int jj  = rem >> 6;
        int e   = rem & 63;
        int k   = e >> 3, i = e & 7;
        Ls[(f * 8 + jj) * 68 + e] = (f <= g && k == i) ? 1.0f : 0.0f;
    }

    // q block -> registers: qreg[i][dd], thread owns (j, d-chunk t8)
    float qreg[8][8];
#pragma unroll
    for (int i = 0; i < 8; i++) {
        const float4* qp = (const float4*)(Q + (i * 8 + j) * 64 + t8 * 8);
        float4 v0 = qp[0], v1 = qp[1];
        qreg[i][0] = v0.x; qreg[i][1] = v0.y; qreg[i][2] = v0.z; qreg[i][3] = v0.w;
        qreg[i][4] = v1.x; qreg[i][5] = v1.y; qreg[i][6] = v1.z; qreg[i][7] = v1.w;
    }
    __syncthreads();

    const int nsteps = 3 * (g + 1);
    issue_tile(0, g, Kp, Vp, Ks_base, tid);
    int step = 0;

    const float NEGINF = __int_as_float(0xff800000);

    for (int it = 0; it < 2; it++) {
        for (int f = 0; f <= g; f++, step++) {
            if (step + 1 < nsteps) {
                issue_tile(step + 1, g, Kp, Vp, Ks_base, tid);
                asm volatile("cp.async.wait_group 1;" ::: "memory");
            } else {
                asm volatile("cp.async.wait_group 0;" ::: "memory");
            }
            __syncthreads();

            const float* kt = Ks + (step & 1) * 4096 + a * 512;   // k-row a: [l][64]
            float* Lrow = Ls + (f * 8 + j) * 68 + a * 8;

            float Lw[8];
#pragma unroll
            for (int i = 0; i < 8; i++) Lw[i] = Lrow[i];
            float cR = 0.f;
#pragma unroll
            for (int i = 0; i < 8; i++) cR += Lw[i];

            // aR[dd] = sum_i Lw[i] * q[i][dd]
            float aR[8];
#pragma unroll
            for (int dd = 0; dd < 8; dd++) {
                float s = 0.f;
#pragma unroll
                for (int i = 0; i < 8; i++) s = fmaf(Lw[i], qreg[i][dd], s);
                aR[dd] = s;
            }

            // bR partials over this thread's d-chunk
            float p[8];
#pragma unroll
            for (int l = 0; l < 8; l++) {
                const float* kv = kt + l * 64 + t8 * 8;
                float s = 0.f;
#pragma unroll
                for (int dd = 0; dd < 8; dd++) s = fmaf(aR[dd], kv[dd], s);
                p[l] = s;
            }
#pragma unroll
            for (int l = 0; l < 8; l++) {
                p[l] += __shfl_xor_sync(0xffffffffu, p[l], 1);
                p[l] += __shfl_xor_sync(0xffffffffu, p[l], 2);
                p[l] += __shfl_xor_sync(0xffffffffu, p[l], 4);
            }

            // softmax over l of bR/(cR+eps)
            float inv = 1.0f / (cR + EPSF);
            float mx = NEGINF;
#pragma unroll
            for (int l = 0; l < 8; l++) { p[l] *= inv; mx = fmaxf(mx, p[l]); }
            float ssum = 0.f;
#pragma unroll
            for (int l = 0; l < 8; l++) { p[l] = __expf(p[l] - mx); ssum += p[l]; }
            float rinv = 1.0f / ssum;
            float cL = 0.f;
#pragma unroll
            for (int l = 0; l < 8; l++) {
                p[l] *= rinv;
                cL = fmaf(p[l], __logf(fmaxf(p[l], 1e-38f)), cL);
            }

            if (t8 == 0) {
                float* rp = Rs + ((f * 8 + a) * 8 + j) * 8;
#pragma unroll
                for (int l = 0; l < 8; l++) rp[l] = p[l];
            }

            // aL[dd] = sum_l R[l] * k[l][dd]
            float aL[8];
#pragma unroll
            for (int dd = 0; dd < 8; dd++) aL[dd] = 0.f;
#pragma unroll
            for (int l = 0; l < 8; l++) {
                const float* kv = kt + l * 64 + t8 * 8;
#pragma unroll
                for (int dd = 0; dd < 8; dd++) aL[dd] = fmaf(p[l], kv[dd], aL[dd]);
            }

            // bL[i] = sum_d aL[dd] * q[i][dd]  (partial, then 8-lane reduce)
            float bL[8];
#pragma unroll
            for (int i = 0; i < 8; i++) {
                float s = 0.f;
#pragma unroll
                for (int dd = 0; dd < 8; dd++) s = fmaf(aL[dd], qreg[i][dd], s);
                bL[i] = s;
            }
#pragma unroll
            for (int i = 0; i < 8; i++) {
                bL[i] += __shfl_xor_sync(0xffffffffu, bL[i], 1);
                bL[i] += __shfl_xor_sync(0xffffffffu, bL[i], 2);
                bL[i] += __shfl_xor_sync(0xffffffffu, bL[i], 4);
            }

            // M overwrite L (same group owns this row segment)
            if (t8 == 0) {
#pragma unroll
                for (int i = 0; i < 8; i++) Lrow[i] = bL[i] - cL;
            }
            __syncthreads();
        }

        // L softmax over (f<=g, k) for each (j, i=a); t8 strides f
        {
            float mx = NEGINF;
            for (int f = t8; f <= g; f += 8) {
                const float* Mr = Ls + (f * 8 + j) * 68;
#pragma unroll
                for (int k = 0; k < 8; k++) mx = fmaxf(mx, Mr[k * 8 + a]);
            }
            mx = fmaxf(mx, __shfl_xor_sync(0xffffffffu, mx, 1));
            mx = fmaxf(mx, __shfl_xor_sync(0xffffffffu, mx, 2));
            mx = fmaxf(mx, __shfl_xor_sync(0xffffffffu, mx, 4));
            float ssum = 0.f;
            for (int f = t8; f <= g; f += 8) {
                const float* Mr = Ls + (f * 8 + j) * 68;
#pragma unroll
                for (int k = 0; k < 8; k++) ssum += __expf(Mr[k * 8 + a] - mx);
            }
            ssum += __shfl_xor_sync(0xffffffffu, ssum, 1);
            ssum += __shfl_xor_sync(0xffffffffu, ssum, 2);
            ssum += __shfl_xor_sync(0xffffffffu, ssum, 4);
            float rs = 1.0f / ssum;
            for (int f = t8; f <= g; f += 8) {
                float* Mr = Ls + (f * 8 + j) * 68;
#pragma unroll
                for (int k = 0; k < 8; k++)
                    Mr[k * 8 + a] = __expf(Mr[k * 8 + a] - mx) * rs;
            }
        }
        __syncthreads();
    }

    // o / out: out[i,j,d] = sum_{f,k} L[f,j,k,i] * (sum_l R[f,k,j,l] v[f,k,l,d])
    float oacc[8];
#pragma unroll
    for (int dd = 0; dd < 8; dd++) oacc[dd] = 0.f;

    for (int f = 0; f <= g; f++, step++) {
        if (step + 1 < nsteps) {
            issue_tile(step + 1, g, Kp, Vp, Ks_base, tid);
            asm volatile("cp.async.wait_group 1;" ::: "memory");
        } else {
            asm volatile("cp.async.wait_group 0;" ::: "memory");
        }
        __syncthreads();

        const float* vt = Ks + (step & 1) * 4096 + a * 512;   // v-row k=a
        // phase A: o_f[k=a][j][dchunk]
        const float* rp = Rs + ((f * 8 + a) * 8 + j) * 8;
        float Rv[8];
#pragma unroll
        for (int l = 0; l < 8; l++) Rv[l] = rp[l];
        float ov[8];
#pragma unroll
        for (int dd = 0; dd < 8; dd++) ov[dd] = 0.f;
#pragma unroll
        for (int l = 0; l < 8; l++) {
            const float* vv = vt + l * 64 + t8 * 8;
#pragma unroll
            for (int dd = 0; dd < 8; dd++) ov[dd] = fmaf(Rv[l], vv[dd], ov[dd]);
        }
        float* op = Os + (a * 8 + j) * 68 + t8 * 8;
#pragma unroll
        for (int dd = 0; dd < 8; dd++) op[dd] = ov[dd];
        __syncthreads();

        // phase B: out[i=a][j][dchunk] += sum_k L[f][j][k][i] * o_f[k][j][dchunk]
        const float* Lrow = Ls + (f * 8 + j) * 68;
#pragma unroll
        for (int k = 0; k < 8; k++) {
            float lw = Lrow[k * 8 + a];
            const float* op2 = Os + (k * 8 + j) * 68 + t8 * 8;
#pragma unroll
            for (int dd = 0; dd < 8; dd++) oacc[dd] = fmaf(lw, op2[dd], oacc[dd]);
        }
        __syncthreads();
    }

    // write out[b][g*64 + i*8 + j][h*64 + d]
    float* po = out + ((size_t)b * SS + g * 64 + a * 8 + j) * DIMM + h * 64 + t8 * 8;
    *(float4*)(po + 0) = make_float4(oacc[0], oacc[1], oacc[2], oacc[3]);
    *(float4*)(po + 4) = make_float4(oacc[4], oacc[5], oacc[6], oacc[7]);
}

// ---------------------------------------------------------------------------
extern "C" void kernel_launch(void* const* d_in, const int* in_sizes, int n_in,
                              void* d_out, int out_size)
{
    const float* x    = (const float*)d_in[0];
    const float* cosT = (const float*)d_in[1];
    const float* sinT = (const float*)d_in[2];
    const float* wq   = (const float*)d_in[3];
    const float* wk   = (const float*)d_in[4];
    const float* wv   = (const float*)d_in[5];
    const float* gq   = (const float*)d_in[6];
    const float* gk   = (const float*)d_in[7];
    float* out = (float*)d_out;

    cudaFuncSetAttribute(monarch_kernel,
                         cudaFuncAttributeMaxDynamicSharedMemorySize, SMEM_BYTES);

    sgemm_nt<<<dim3(8, 32, 3), 256>>>(x, wq, wk, wv);
    qkv_epilogue<<<(BB * SS * HH) / 4, 128>>>(cosT, sinT, gq, gk);
    monarch_kernel<<<dim3(FF, HH, BB), 512, SMEM_BYTES>>>(out);
}

// round 16
// speedup vs baseline: 1.3589x; 1.3582x over previous
#include <cuda_runtime.h>
#include <cuda_bf16.h>
#include <cstdint>

// Problem constants
#define BB   2
#define SS   2048
#define DIMM 1024
#define HH   16
#define DD   64
#define FF   32      // S / 64
#define EPSF 1e-6f

// Scratch (static device globals; no dynamic allocation)
__device__ float g_raw[3][BB * SS * DIMM];        // raw projections [b,s,dim]
__device__ float g_T[3][BB * HH * SS * DD];       // q,k,v in [b,h,s,d]
__device__ __nv_bfloat16 g_xhi[BB * SS * DIMM];
__device__ __nv_bfloat16 g_xlo[BB * SS * DIMM];
__device__ __nv_bfloat16 g_whi[3][DIMM * DIMM];
__device__ __nv_bfloat16 g_wlo[3][DIMM * DIMM];

// ---------------------------------------------------------------------------
// Split fp32 -> (bf16 hi, bf16 lo) for x and the three weights.
// ---------------------------------------------------------------------------
__global__ __launch_bounds__(256) void convert_split(const float* __restrict__ x,
                                                     const float* __restrict__ wq,
                                                     const float* __restrict__ wk,
                                                     const float* __restrict__ wv)
{
    int idx = blockIdx.x * 256 + threadIdx.x;
    const int NX = BB * SS * DIMM;              // 4M
    const int NW = DIMM * DIMM;                 // 1M (power of two)
    float v;
    __nv_bfloat16 *hip, *lop;
    if (idx < NX) {
        v = x[idx]; hip = &g_xhi[idx]; lop = &g_xlo[idx];
    } else {
        int r = idx - NX;
        int w = r >> 20;                        // NW = 2^20
        int o = r & (NW - 1);
        const float* W = (w == 0) ? wq : (w == 1 ? wk : wv);
        v = W[o]; hip = &g_whi[w][o]; lop = &g_wlo[w][o];
    }
    __nv_bfloat16 h = __float2bfloat16(v);
    *hip = h;
    *lop = __float2bfloat16(v - __bfloat162float(h));
}

// ---------------------------------------------------------------------------
// Tensor-core GEMM via mma.sync (baseline PTX, works on compute_103):
// C[m,n] = sum_k X[m,k] * W[n,k] with 3-term bf16 split.
// CTA tile 128x128, k-chunks of 32, double-buffered cp.async smem.
// 8 warps, each computes a 32(m) x 64(n) warp tile with m16n8k16 MMAs.
// Smem rows padded to 40 bf16 (80B) -> conflict-free ldmatrix.
// ---------------------------------------------------------------------------
#define TSTR   40                       // bf16 per smem row (32 data + 8 pad)
#define TILE_B (128 * TSTR * 2)         // 10240 bytes per 128x32 tile
#define BUF_B  (4 * TILE_B)             // Ahi, Alo, Bhi, Blo
#define MM_SMEM (2 * BUF_B)             // 81920 bytes (double buffer)

__device__ __forceinline__ uint32_t smem_u32(const void* p) {
    return (uint32_t)__cvta_generic_to_shared(p);
}

__device__ __forceinline__ void ldsm_x4(uint32_t* d, uint32_t addr) {
    asm volatile("ldmatrix.sync.aligned.m8n8.x4.shared.b16 {%0,%1,%2,%3}, [%4];"
                 : "=r"(d[0]), "=r"(d[1]), "=r"(d[2]), "=r"(d[3]) : "r"(addr));
}

__device__ __forceinline__ void mma16816(float* c, const uint32_t* a, const uint32_t* b) {
    asm volatile("mma.sync.aligned.m16n8k16.row.col.f32.bf16.bf16.f32 "
                 "{%0,%1,%2,%3}, {%4,%5,%6,%7}, {%8,%9}, {%0,%1,%2,%3};"
                 : "+f"(c[0]), "+f"(c[1]), "+f"(c[2]), "+f"(c[3])
                 : "r"(a[0]), "r"(a[1]), "r"(a[2]), "r"(a[3]),
                   "r"(b[0]), "r"(b[1]));
}

__global__ void __launch_bounds__(256, 1) mma_gemm()
{
    extern __shared__ __nv_bfloat16 smem_bf[];
    const uint32_t sbase = smem_u32(smem_bf);

    const int z  = blockIdx.z;
    const int m0 = blockIdx.y * 128;
    const int n0 = blockIdx.x * 128;
    const int tid  = threadIdx.x;
    const int lane = tid & 31;
    const int warp = tid >> 5;
    const int wm = (warp & 3) * 32;       // warp m-offset within CTA tile
    const int wn = (warp >> 2) * 64;      // warp n-offset

    const __nv_bfloat16* Ahi_g = g_xhi    + (size_t)m0 * 1024;
    const __nv_bfloat16* Alo_g = g_xlo    + (size_t)m0 * 1024;
    const __nv_bfloat16* Bhi_g = g_whi[z] + (size_t)n0 * 1024;
    const __nv_bfloat16* Blo_g = g_wlo[z] + (size_t)n0 * 1024;

    float acc[2][8][4];
#pragma unroll
    for (int mi = 0; mi < 2; mi++)
#pragma unroll
        for (int ni = 0; ni < 8; ni++)
#pragma unroll
            for (int q = 0; q < 4; q++) acc[mi][ni][q] = 0.f;

    // ---- chunk loader: 4 tiles of 128 rows x 32 bf16 (16B per cp.async) ----
    auto load_chunk = [&](int c, int buf) {
        uint32_t base = sbase + (uint32_t)buf * BUF_B;
        int k0 = c * 32;
#pragma unroll
        for (int u = 0; u < 8; u++) {
            const int t = u >> 1;                       // compile-time tile id
            int w = tid + (u & 1) * 256;                // 0..511
            int row = w >> 2, q = w & 3;
            const __nv_bfloat16* gp = (t == 0) ? Ahi_g : (t == 1) ? Alo_g
                                      : (t == 2) ? Bhi_g : Blo_g;
            const void* src = gp + (size_t)row * 1024 + k0 + q * 8;
            uint32_t dst = base + t * TILE_B + (uint32_t)(row * TSTR + q * 8) * 2;
            asm volatile("cp.async.cg.shared.global [%0], [%1], 16;"
                         :: "r"(dst), "l"(src) : "memory");
        }
        asm volatile("cp.async.commit_group;" ::: "memory");
    };

    // ---- per-warp compute on one buffered chunk ----
    const int r  = lane & 7;
    const int tl = lane >> 3;
    auto compute = [&](int buf) {
        uint32_t base = sbase + (uint32_t)buf * BUF_B;
#pragma unroll
        for (int ksub = 0; ksub < 2; ksub++) {
            uint32_t ah[2][4], al[2][4];
#pragma unroll
            for (int mi = 0; mi < 2; mi++) {
                int arow = wm + mi * 16 + (tl & 1) * 8 + r;
                int acol = (tl >> 1) * 8 + ksub * 16;
                uint32_t aaddr = base + (uint32_t)(arow * TSTR + acol) * 2;
                ldsm_x4(ah[mi], aaddr);
                ldsm_x4(al[mi], aaddr + TILE_B);
            }
#pragma unroll
            for (int np = 0; np < 4; np++) {
                int brow = wn + np * 16 + (tl >> 1) * 8 + r;
                int bcol = (tl & 1) * 8 + ksub * 16;
                uint32_t baddr = base + 2 * TILE_B + (uint32_t)(brow * TSTR + bcol) * 2;
                uint32_t bh[4], bl[4];
                ldsm_x4(bh, baddr);
                ldsm_x4(bl, baddr + TILE_B);
#pragma unroll
                for (int mi = 0; mi < 2; mi++) {
                    mma16816(acc[mi][2 * np    ], ah[mi], bh + 0);
                    mma16816(acc[mi][2 * np + 1], ah[mi], bh + 2);
                    mma16816(acc[mi][2 * np    ], ah[mi], bl + 0);
                    mma16816(acc[mi][2 * np + 1], ah[mi], bl + 2);
                    mma16816(acc[mi][2 * np    ], al[mi], bh + 0);
                    mma16816(acc[mi][2 * np + 1], al[mi], bh + 2);
                }
            }
        }
    };

    load_chunk(0, 0);
    load_chunk(1, 1);
    for (int c = 0; c < 32; c++) {
        if (c < 31) asm volatile("cp.async.wait_group 1;" ::: "memory");
        else        asm volatile("cp.async.wait_group 0;" ::: "memory");
        __syncthreads();
        compute(c & 1);
        __syncthreads();
        if (c + 2 < 32) load_chunk(c + 2, c & 1);
    }

    // ---- epilogue: write fp32 C ----
    float* C = g_raw[z];
    int rbase = m0 + wm + (lane >> 2);
    int cbase = n0 + wn + (lane & 3) * 2;
#pragma unroll
    for (int mi = 0; mi < 2; mi++) {
#pragma unroll
        for (int ni = 0; ni < 8; ni++) {
            int row = rbase + mi * 16;
            int col = cbase + ni * 8;
            *(float2*)(C + (size_t)row * 1024 + col) =
                make_float2(acc[mi][ni][0], acc[mi][ni][1]);
            *(float2*)(C + (size_t)(row + 8) * 1024 + col) =
                make_float2(acc[mi][ni][2], acc[mi][ni][3]);
        }
    }
}

// ---------------------------------------------------------------------------
// Epilogue: rmsnorm(q,k) + rope + scale, transpose all to [b,h,s,d]
// ---------------------------------------------------------------------------
__global__ __launch_bounds__(128) void qkv_epilogue(const float* __restrict__ cosT,
                                                    const float* __restrict__ sinT,
                                                    const float* __restrict__ gq,
                                                    const float* __restrict__ gk)
{
    int warp = blockIdx.x * 4 + (threadIdx.x >> 5);
    int lane = threadIdx.x & 31;
    int h  = warp & 15;
    int bs = warp >> 4;           // b*S + s
    int s  = bs & (SS - 1);
    int b  = bs >> 11;
    int d0 = lane * 2, d1 = d0 + 1;
    size_t src = (size_t)bs * 1024 + h * 64;
    size_t dst = ((size_t)(b * HH + h) * SS + s) * 64;

    float c  = cosT[s * 64 + d0];
    float sn = sinT[s * 64 + d0];
    const float SCALE = 0.35355339059327373f;   // 64^-0.25

    // Q
    {
        float x0 = g_raw[0][src + d0], x1 = g_raw[0][src + d1];
        float ssum = x0 * x0 + x1 * x1;
#pragma unroll
        for (int m = 16; m > 0; m >>= 1) ssum += __shfl_xor_sync(0xffffffffu, ssum, m);
        float r = rsqrtf(ssum * (1.0f / 64.0f) + EPSF);
        x0 *= r * gq[d0]; x1 *= r * gq[d1];
        g_T[0][dst + d0] = (x0 * c - x1 * sn) * SCALE;
        g_T[0][dst + d1] = (x1 * c + x0 * sn) * SCALE;
    }
    // K
    {
        float x0 = g_raw[1][src + d0], x1 = g_raw[1][src + d1];
        float ssum = x0 * x0 + x1 * x1;
#pragma unroll
        for (int m = 16; m > 0; m >>= 1) ssum += __shfl_xor_sync(0xffffffffu, ssum, m);
        float r = rsqrtf(ssum * (1.0f / 64.0f) + EPSF);
        x0 *= r * gk[d0]; x1 *= r * gk[d1];
        g_T[1][dst + d0] = (x0 * c - x1 * sn) * SCALE;
        g_T[1][dst + d1] = (x1 * c + x0 * sn) * SCALE;
    }
    // V (plain transpose)
    g_T[2][dst + d0] = g_raw[2][src + d0];
    g_T[2][dst + d1] = g_raw[2][src + d1];
}

// ---------------------------------------------------------------------------
// Monarch iterations. One CTA per (b,h,g). 256 threads (best-known config).
// group = tid/4 -> (a = group/8 [=warp id], j = group%8), t4 = tid%4 (d-chunk of 16).
// ---------------------------------------------------------------------------
#define LS_FLOATS  (32 * 8 * 68)          // 17408
#define RS_FLOATS  (32 * 8 * 8 * 8)       // 16384
#define KS_FLOATS  (2 * 4096)             // 8192
#define OS_FLOATS  (64 * 68)              // 4352
#define SMEM_FLOATS (LS_FLOATS + RS_FLOATS + KS_FLOATS + OS_FLOATS)
#define SMEM_BYTES  (SMEM_FLOATS * 4)

__device__ __forceinline__ void issue_tile(int step, int g,
                                           const float* __restrict__ Kp,
                                           const float* __restrict__ Vp,
                                           uint32_t Ks_base, int tid)
{
    int per   = g + 1;
    int phase = step / per;                  // 0,1 -> K ; 2 -> V
    int f     = step - phase * per;
    const float* src = ((phase < 2) ? Kp : Vp) + (size_t)f * 4096;
    uint32_t dstb = Ks_base + (uint32_t)(step & 1) * (4096u * 4u);
#pragma unroll
    for (int u = 0; u < 4; u++) {
        int idx4 = tid + u * 256;
        asm volatile("cp.async.cg.shared.global [%0], [%1], 16;"
                     :: "r"(dstb + idx4 * 16), "l"(src + idx4 * 4) : "memory");
    }
    asm volatile("cp.async.commit_group;" ::: "memory");
}

__global__ void __launch_bounds__(256, 1) monarch_kernel(float* __restrict__ out)
{
    const int g = (FF - 1) - blockIdx.x;   // largest work first
    const int h = blockIdx.y, b = blockIdx.z;
    const int tid = threadIdx.x;
    const int t4  = tid & 3;
    const int grp = tid >> 2;
    const int j   = grp & 7;
    const int a   = grp >> 3;    // warp id

    extern __shared__ float sm[];
    float* Ls = sm;
    float* Rs = sm + LS_FLOATS;
    float* Ks = Rs + RS_FLOATS;
    float* Os = Ks + KS_FLOATS;
    uint32_t Ks_base = (uint32_t)__cvta_generic_to_shared(Ks);

    const int bh = b * HH + h;
    const float* Q  = g_T[0] + ((size_t)bh * SS + g * 64) * 64;
    const float* Kp = g_T[1] + (size_t)bh * SS * 64;
    const float* Vp = g_T[2] + (size_t)bh * SS * 64;

    // init L[f][j][k][i] = (f<=g) * delta(k,i)
    for (int idx = tid; idx < 32 * 8 * 64; idx += 256) {
        int f   = idx >> 9;
        int rem = idx & 511;
        int jj  = rem >> 6;
        int e   = rem & 63;
        int k   = e >> 3, i = e & 7;
        Ls[(f * 8 + jj) * 68 + e] = (f <= g && k == i) ? 1.0f : 0.0f;
    }

    // q block -> registers: qreg[i][dd], thread owns (j, d-chunk t4)
    float qreg[8][16];
#pragma unroll
    for (int i = 0; i < 8; i++) {
        const float4* qp = (const float4*)(Q + (i * 8 + j) * 64 + t4 * 16);
#pragma unroll
        for (int u = 0; u < 4; u++) {
            float4 v = qp[u];
            qreg[i][u * 4 + 0] = v.x; qreg[i][u * 4 + 1] = v.y;
            qreg[i][u * 4 + 2] = v.z; qreg[i][u * 4 + 3] = v.w;
        }
    }
    __syncthreads();

    const int nsteps = 3 * (g + 1);
    issue_tile(0, g, Kp, Vp, Ks_base, tid);
    int step = 0;

    const float NEGINF = __int_as_float(0xff800000);

    for (int it = 0; it < 2; it++) {
        for (int f = 0; f <= g; f++, step++) {
            if (step + 1 < nsteps) {
                issue_tile(step + 1, g, Kp, Vp, Ks_base, tid);
                asm volatile("cp.async.wait_group 1;" ::: "memory");
            } else {
                asm volatile("cp.async.wait_group 0;" ::: "memory");
            }
            __syncthreads();

            const float* kt = Ks + (step & 1) * 4096 + a * 512;   // k-row a: [l][64]
            float* Lrow = Ls + (f * 8 + j) * 68 + a * 8;

            float Lw[8];
#pragma unroll
            for (int i = 0; i < 8; i++) Lw[i] = Lrow[i];
            float cR = 0.f;
#pragma unroll
            for (int i = 0; i < 8; i++) cR += Lw[i];

            // aR[dd] = sum_i Lw[i] * q[i][dd]
            float aR[16];
#pragma unroll
            for (int dd = 0; dd < 16; dd++) {
                float s = 0.f;
#pragma unroll
                for (int i = 0; i < 8; i++) s = fmaf(Lw[i], qreg[i][dd], s);
                aR[dd] = s;
            }

            // bR partials over this thread's d-chunk
            float p[8];
#pragma unroll
            for (int l = 0; l < 8; l++) {
                const float* kv = kt + l * 64 + t4 * 16;
                float s = 0.f;
#pragma unroll
                for (int dd = 0; dd < 16; dd++) s = fmaf(aR[dd], kv[dd], s);
                p[l] = s;
            }
#pragma unroll
            for (int l = 0; l < 8; l++) {
                p[l] += __shfl_xor_sync(0xffffffffu, p[l], 1);
                p[l] += __shfl_xor_sync(0xffffffffu, p[l], 2);
            }

            // softmax over l of bR/(cR+eps)
            float inv = 1.0f / (cR + EPSF);
            float mx = NEGINF;
#pragma unroll
            for (int l = 0; l < 8; l++) { p[l] *= inv; mx = fmaxf(mx, p[l]); }
            float ssum = 0.f;
#pragma unroll
            for (int l = 0; l < 8; l++) { p[l] = __expf(p[l] - mx); ssum += p[l]; }
            float rinv = 1.0f / ssum;
            float cL = 0.f;
#pragma unroll
            for (int l = 0; l < 8; l++) {
                p[l] *= rinv;
                cL = fmaf(p[l], __logf(fmaxf(p[l], 1e-38f)), cL);
            }

            if (t4 == 0) {
                float* rp = Rs + ((f * 8 + a) * 8 + j) * 8;
#pragma unroll
                for (int l = 0; l < 8; l++) rp[l] = p[l];
            }

            // aL[dd] = sum_l R[l] * k[l][dd]
            float aL[16];
#pragma unroll
            for (int dd = 0; dd < 16; dd++) aL[dd] = 0.f;
#pragma unroll
            for (int l = 0; l < 8; l++) {
                const float* kv = kt + l * 64 + t4 * 16;
#pragma unroll
                for (int dd = 0; dd < 16; dd++) aL[dd] = fmaf(p[l], kv[dd], aL[dd]);
            }

            // bL[i] = sum_d aL[dd] * q[i][dd]  (partial, then 4-lane reduce)
            float bL[8];
#pragma unroll
            for (int i = 0; i < 8; i++) {
                float s = 0.f;
#pragma unroll
                for (int dd = 0; dd < 16; dd++) s = fmaf(aL[dd], qreg[i][dd], s);
                bL[i] = s;
            }
#pragma unroll
            for (int i = 0; i < 8; i++) {
                bL[i] += __shfl_xor_sync(0xffffffffu, bL[i], 1);
                bL[i] += __shfl_xor_sync(0xffffffffu, bL[i], 2);
            }

            // M overwrite L (same group owns this row segment)
            if (t4 == 0) {
#pragma unroll
                for (int i = 0; i < 8; i++) Lrow[i] = bL[i] - cL;
            }
            __syncthreads();
        }

        // L softmax over (f<=g, k) for each (j, i=a); t4 strides f
        {
            float mx = NEGINF;
            for (int f = t4; f <= g; f += 4) {
                const float* Mr = Ls + (f * 8 + j) * 68;
#pragma unroll
                for (int k = 0; k < 8; k++) mx = fmaxf(mx, Mr[k * 8 + a]);
            }
            mx = fmaxf(mx, __shfl_xor_sync(0xffffffffu, mx, 1));
            mx = fmaxf(mx, __shfl_xor_sync(0xffffffffu, mx, 2));
            float ssum = 0.f;
            for (int f = t4; f <= g; f += 4) {
                const float* Mr = Ls + (f * 8 + j) * 68;
#pragma unroll
                for (int k = 0; k < 8; k++) ssum += __expf(Mr[k * 8 + a] - mx);
            }
            ssum += __shfl_xor_sync(0xffffffffu, ssum, 1);
            ssum += __shfl_xor_sync(0xffffffffu, ssum, 2);
            float rs = 1.0f / ssum;
            for (int f = t4; f <= g; f += 4) {
                float* Mr = Ls + (f * 8 + j) * 68;
#pragma unroll
                for (int k = 0; k < 8; k++)
                    Mr[k * 8 + a] = __expf(Mr[k * 8 + a] - mx) * rs;
            }
        }
        __syncthreads();
    }

    // o / out: out[i,j,d] = sum_{f,k} L[f,j,k,i] * (sum_l R[f,k,j,l] v[f,k,l,d])
    float oacc[16];
#pragma unroll
    for (int dd = 0; dd < 16; dd++) oacc[dd] = 0.f;

    for (int f = 0; f <= g; f++, step++) {
        if (step + 1 < nsteps) {
            issue_tile(step + 1, g, Kp, Vp, Ks_base, tid);
            asm volatile("cp.async.wait_group 1;" ::: "memory");
        } else {
            asm volatile("cp.async.wait_group 0;" ::: "memory");
        }
        __syncthreads();

        const float* vt = Ks + (step & 1) * 4096 + a * 512;   // v-row k=a
        // phase A: o_f[k=a][j][dchunk]
        const float* rp = Rs + ((f * 8 + a) * 8 + j) * 8;
        float Rv[8];
#pragma unroll
        for (int l = 0; l < 8; l++) Rv[l] = rp[l];
        float ov[16];
#pragma unroll
        for (int dd = 0; dd < 16; dd++) ov[dd] = 0.f;
#pragma unroll
        for (int l = 0; l < 8; l++) {
            const float* vv = vt + l * 64 + t4 * 16;
#pragma unroll
            for (int dd = 0; dd < 16; dd++) ov[dd] = fmaf(Rv[l], vv[dd], ov[dd]);
        }
        float* op = Os + (a * 8 + j) * 68 + t4 * 16;
#pragma unroll
        for (int dd = 0; dd < 16; dd++) op[dd] = ov[dd];
        __syncthreads();

        // phase B: out[i=a][j][dchunk] += sum_k L[f][j][k][i] * o_f[k][j][dchunk]
        const float* Lrow = Ls + (f * 8 + j) * 68;
#pragma unroll
        for (int k = 0; k < 8; k++) {
            float lw = Lrow[k * 8 + a];
            const float* op2 = Os + (k * 8 + j) * 68 + t4 * 16;
#pragma unroll
            for (int dd = 0; dd < 16; dd++) oacc[dd] = fmaf(lw, op2[dd], oacc[dd]);
        }
        __syncthreads();
    }

    // write out[b][g*64 + i*8 + j][h*64 + d]
    float* po = out + ((size_t)b * SS + g * 64 + a * 8 + j) * DIMM + h * 64 + t4 * 16;
#pragma unroll
    for (int dd = 0; dd < 16; dd += 4) {
        float4 v = make_float4(oacc[dd], oacc[dd + 1], oacc[dd + 2], oacc[dd + 3]);
        *(float4*)(po + dd) = v;
    }
}

// ---------------------------------------------------------------------------
extern "C" void kernel_launch(void* const* d_in, const int* in_sizes, int n_in,
                              void* d_out, int out_size)
{
    const float* x    = (const float*)d_in[0];
    const float* cosT = (const float*)d_in[1];
    const float* sinT = (const float*)d_in[2];
    const float* wq   = (const float*)d_in[3];
    const float* wk   = (const float*)d_in[4];
    const float* wv   = (const float*)d_in[5];
    const float* gq   = (const float*)d_in[6];
    const float* gk   = (const float*)d_in[7];
    float* out = (float*)d_out;

    cudaFuncSetAttribute(mma_gemm,
                         cudaFuncAttributeMaxDynamicSharedMemorySize, MM_SMEM);
    cudaFuncSetAttribute(monarch_kernel,
                         cudaFuncAttributeMaxDynamicSharedMemorySize, SMEM_BYTES);

    const int NTOT = BB * SS * DIMM + 3 * DIMM * DIMM;   // 7,340,032
    convert_split<<<NTOT / 256, 256>>>(x, wq, wk, wv);
    mma_gemm<<<dim3(8, 32, 3), 256, MM_SMEM>>>();
    qkv_epilogue<<<(BB * SS * HH) / 4, 128>>>(cosT, sinT, gq, gk);
    monarch_kernel<<<dim3(FF, HH, BB), 256, SMEM_BYTES>>>(out);
}